// round 2
// baseline (speedup 1.0000x reference)
#include <cuda_runtime.h>
#include <cuda_bf16.h>

#define RES 300
#define NCH 64            // NC_A + NC_D
#define NC_A 48
#define APP_DIM 27
#define KDIM (3*NC_A)     // 144
#define ROWPAD 148        // smem row stride in floats (conflict-free for ld.128)

// Scratch: transposed planes [3][y][x][c] and lines [3][y][c]
__device__ float g_planeT[3 * RES * RES * NCH];     // 69.1 MB
__device__ float g_lineT[3 * RES * NCH];            // 230 KB
__constant__ float c_W[APP_DIM * KDIM];             // basis_W, [d][k] row-major

// ---------------- transpose planes: (3,64,300,300) -> [3][y][x][64] ----------------
__global__ void transpose_planes_k(const float* __restrict__ in) {
    __shared__ float tile[32][33];
    int iy = blockIdx.z;                 // i*RES + y
    int i = iy / RES, y = iy - i * RES;
    int x0 = blockIdx.x * 32, c0 = blockIdx.y * 32;
#pragma unroll
    for (int j = 0; j < 4; j++) {
        int c = c0 + threadIdx.y + j * 8;
        int x = x0 + threadIdx.x;
        float v = 0.f;
        if (x < RES) v = in[((i * NCH + c) * RES + y) * RES + x];   // coalesced in x
        tile[threadIdx.y + j * 8][threadIdx.x] = v;
    }
    __syncthreads();
#pragma unroll
    for (int j = 0; j < 4; j++) {
        int x = x0 + threadIdx.y + j * 8;
        int c = c0 + threadIdx.x;
        if (x < RES)                                                 // coalesced in c
            g_planeT[((i * RES + y) * RES + x) * NCH + c] = tile[threadIdx.x][threadIdx.y + j * 8];
    }
}

// ---------------- transpose lines: (3,64,300,1) -> [3][y][64] ----------------
__global__ void transpose_lines_k(const float* __restrict__ in) {
    int t = blockIdx.x * 256 + threadIdx.x;
    if (t >= 3 * RES * NCH) return;
    int c = t & 63;
    int rest = t >> 6;
    int y = rest % RES;
    int i = rest / RES;
    g_lineT[t] = in[(i * NCH + c) * RES + y];
}

// ---------------- main: gather + density reduce + app GEMM ----------------
__global__ __launch_bounds__(128, 2)
void tensorf_main(const float* __restrict__ xyz,
                  float* __restrict__ outSigma,
                  float* __restrict__ outApp,
                  int N) {
    extern __shared__ float smemV[];     // [128][ROWPAD]
    const int tid  = threadIdx.x;
    const int lane = tid & 31;
    const int w    = tid >> 5;
    const int blockStart = blockIdx.x * 128;

    // ---- Phase 1: warp-cooperative gather (lane = channel), 32 samples/warp ----
    {
        int sbase = blockStart + w * 32;
        int n0 = sbase + lane;
        float mx = 0.f, my = 0.f, mz = 0.f;
        if (n0 < N) {
            mx = xyz[(size_t)n0 * 3 + 0];
            my = xyz[(size_t)n0 * 3 + 1];
            mz = xyz[(size_t)n0 * 3 + 2];
        }
        for (int s = 0; s < 32; s++) {
            int n = sbase + s;
            if (n >= N) break;   // uniform across warp
            float X = __shfl_sync(0xFFFFFFFFu, mx, s);
            float Y = __shfl_sync(0xFFFFFFFFu, my, s);
            float Z = __shfl_sync(0xFFFFFFFFu, mz, s);
            // MAT_MODE = [[0,1],[0,2],[1,2]], VEC_MODE = [2,1,0]
            float cs0[3] = {X, X, Y};
            float cs1[3] = {Y, Z, Z};
            float csv[3] = {Z, Y, X};
            float dens = 0.f;
            float* vrow = smemV + (w * 32 + s) * ROWPAD;
#pragma unroll
            for (int i = 0; i < 3; i++) {
                // ---- plane bilinear (align_corners=True, zero pad) ----
                float ix = (cs0[i] + 1.f) * 149.5f;
                float iy = (cs1[i] + 1.f) * 149.5f;
                float fx = floorf(ix), fy = floorf(iy);
                float wx = ix - fx, wy = iy - fy;
                int xi = (int)fx, yi = (int)fy;
                float w1x = (xi + 1 >= 0 && xi + 1 < RES) ? wx : 0.f;
                float w0x = (xi >= 0 && xi < RES) ? (1.f - wx) : 0.f;
                float w1y = (yi + 1 >= 0 && yi + 1 < RES) ? wy : 0.f;
                float w0y = (yi >= 0 && yi < RES) ? (1.f - wy) : 0.f;
                int x0c = min(max(xi, 0), RES - 1), x1c = min(max(xi + 1, 0), RES - 1);
                int y0c = min(max(yi, 0), RES - 1), y1c = min(max(yi + 1, 0), RES - 1);
                const float* pb  = g_planeT + (size_t)i * RES * RES * NCH;
                const float* p00 = pb + (y0c * RES + x0c) * NCH;
                const float* p01 = pb + (y0c * RES + x1c) * NCH;
                const float* p10 = pb + (y1c * RES + x0c) * NCH;
                const float* p11 = pb + (y1c * RES + x1c) * NCH;
                float w00 = w0x * w0y, w01 = w1x * w0y, w10 = w0x * w1y, w11 = w1x * w1y;
                float f0 = w00 * p00[lane]      + w01 * p01[lane]
                         + w10 * p10[lane]      + w11 * p11[lane];
                float f1 = w00 * p00[lane + 32] + w01 * p01[lane + 32]
                         + w10 * p10[lane + 32] + w11 * p11[lane + 32];
                // ---- line 1-D interp ----
                float iv = (csv[i] + 1.f) * 149.5f;
                float fv = floorf(iv);
                float wv = iv - fv;
                int vi = (int)fv;
                float wv1 = (vi + 1 >= 0 && vi + 1 < RES) ? wv : 0.f;
                float wv0 = (vi >= 0 && vi < RES) ? (1.f - wv) : 0.f;
                int v0c = min(max(vi, 0), RES - 1), v1c = min(max(vi + 1, 0), RES - 1);
                const float* l0 = g_lineT + (i * RES + v0c) * NCH;
                const float* l1 = g_lineT + (i * RES + v1c) * NCH;
                float lf0 = wv0 * l0[lane]      + wv1 * l1[lane];
                float lf1 = wv0 * l0[lane + 32] + wv1 * l1[lane + 32];

                float p0 = f0 * lf0;             // channel c = lane       (0..31, app)
                float p1 = f1 * lf1;             // channel c = lane + 32
                vrow[i * NC_A + lane] = p0;
                if (lane < 16) vrow[i * NC_A + 32 + lane] = p1;   // app ch 32..47
                else           dens += p1;                        // density ch 48..63
            }
            // reduce density over lanes 16..31 (closed under xor<16)
            dens += __shfl_xor_sync(0xFFFFFFFFu, dens, 1);
            dens += __shfl_xor_sync(0xFFFFFFFFu, dens, 2);
            dens += __shfl_xor_sync(0xFFFFFFFFu, dens, 4);
            dens += __shfl_xor_sync(0xFFFFFFFFu, dens, 8);
            if (lane == 16) outSigma[n] = dens;
        }
    }
    __syncthreads();

    // ---- Phase 2: per-thread app GEMM (1 sample x 27 outputs, W in constant) ----
    {
        int n = blockStart + tid;
        float acc[APP_DIM];
#pragma unroll
        for (int d = 0; d < APP_DIM; d++) acc[d] = 0.f;
        if (n < N) {
            const float* row = smemV + tid * ROWPAD;
#pragma unroll 1
            for (int k4 = 0; k4 < KDIM; k4 += 4) {
                float4 v4 = *reinterpret_cast<const float4*>(row + k4);
                float vv[4] = {v4.x, v4.y, v4.z, v4.w};
#pragma unroll
                for (int j = 0; j < 4; j++) {
#pragma unroll
                    for (int d = 0; d < APP_DIM; d++)
                        acc[d] = fmaf(vv[j], c_W[d * KDIM + k4 + j], acc[d]);
                }
            }
        }
        __syncthreads();   // everyone done reading their v-row
        if (n < N) {
            float* rw = smemV + tid * ROWPAD;
#pragma unroll
            for (int d = 0; d < APP_DIM; d++) rw[d] = acc[d];
        }
        __syncthreads();
        // cooperative, coalesced store of app features
        int nblk = min(128, N - blockStart);
        if (nblk > 0) {
            int total = nblk * APP_DIM;
            size_t obase = (size_t)blockStart * APP_DIM;
            for (int idx = tid; idx < total; idx += 128) {
                int s = idx / APP_DIM;
                int d = idx - s * APP_DIM;
                outApp[obase + idx] = smemV[s * ROWPAD + d];
            }
        }
    }
}

extern "C" void kernel_launch(void* const* d_in, const int* in_sizes, int n_in,
                              void* d_out, int out_size) {
    const float* xyz   = (const float*)d_in[0];
    const float* plane = (const float*)d_in[1];
    const float* line  = (const float*)d_in[2];
    const float* W     = (const float*)d_in[3];
    int N = in_sizes[0] / 3;

    float* outSigma = (float*)d_out;
    float* outApp   = outSigma + N;

    (void)cudaFuncSetAttribute(tensorf_main,
                               cudaFuncAttributeMaxDynamicSharedMemorySize,
                               128 * ROWPAD * sizeof(float));

    cudaMemcpyToSymbolAsync(c_W, W, sizeof(float) * APP_DIM * KDIM, 0,
                            cudaMemcpyDeviceToDevice, 0);

    transpose_planes_k<<<dim3((RES + 31) / 32, NCH / 32, 3 * RES), dim3(32, 8)>>>(plane);
    transpose_lines_k<<<(3 * RES * NCH + 255) / 256, 256>>>(line);

    int grid = (N + 127) / 128;
    tensorf_main<<<grid, 128, 128 * ROWPAD * sizeof(float)>>>(xyz, outSigma, outApp, N);
}

// round 3
// speedup vs baseline: 1.5114x; 1.5114x over previous
#include <cuda_runtime.h>
#include <cuda_bf16.h>

#define RES 300
#define NCH 64            // NC_A + NC_D
#define NC_A 48
#define APP_DIM 27
#define KDIM (3*NC_A)     // 144
#define NPAIR 14          // ceil(27/2)
#define ROWPAD 148        // smem row stride in floats (37 x 16B chunks, odd -> conflict-free ld.128)

// Scratch: transposed planes [3][y][x][c] and lines [3][y][c]
__device__ float g_planeT[3 * RES * RES * NCH];           // 69.1 MB
__device__ float g_lineT[3 * RES * NCH];                  // 230 KB
__device__ ulonglong2 g_W2v[KDIM * NPAIR / 2];            // packed W staging (device side)
__constant__ ulonglong2 c_W2v[KDIM * NPAIR / 2];          // [k][7] of 2x f32x2 pairs

// ---------------- transpose planes: (3,64,300,300) -> [3][y][x][64] ----------------
__global__ void transpose_planes_k(const float* __restrict__ in) {
    __shared__ float tile[32][33];
    int iy = blockIdx.z;                 // i*RES + y
    int i = iy / RES, y = iy - i * RES;
    int x0 = blockIdx.x * 32, c0 = blockIdx.y * 32;
#pragma unroll
    for (int j = 0; j < 4; j++) {
        int c = c0 + threadIdx.y + j * 8;
        int x = x0 + threadIdx.x;
        float v = 0.f;
        if (x < RES) v = in[((i * NCH + c) * RES + y) * RES + x];   // coalesced in x
        tile[threadIdx.y + j * 8][threadIdx.x] = v;
    }
    __syncthreads();
#pragma unroll
    for (int j = 0; j < 4; j++) {
        int x = x0 + threadIdx.y + j * 8;
        int c = c0 + threadIdx.x;
        if (x < RES)                                                 // coalesced in c
            g_planeT[((i * RES + y) * RES + x) * NCH + c] = tile[threadIdx.x][threadIdx.y + j * 8];
    }
}

// ---------------- transpose lines: (3,64,300,1) -> [3][y][64] ----------------
__global__ void transpose_lines_k(const float* __restrict__ in) {
    int t = blockIdx.x * 256 + threadIdx.x;
    if (t >= 3 * RES * NCH) return;
    int c = t & 63;
    int rest = t >> 6;
    int y = rest % RES;
    int i = rest / RES;
    g_lineT[t] = in[(i * NCH + c) * RES + y];
}

// ---------------- pack basis_W: [27][144] -> k-major f32x2 pairs ----------------
__global__ void pack_W_k(const float* __restrict__ W) {
    int t = blockIdx.x * 256 + threadIdx.x;       // over KDIM*NPAIR = 2016
    if (t >= KDIM * NPAIR) return;
    int k = t / NPAIR, jj = t - k * NPAIR;
    int d0 = 2 * jj, d1 = 2 * jj + 1;
    float lo = W[d0 * KDIM + k];
    float hi = (d1 < APP_DIM) ? W[d1 * KDIM + k] : 0.f;
    unsigned long long v = ((unsigned long long)__float_as_uint(hi) << 32)
                         | (unsigned long long)__float_as_uint(lo);
    reinterpret_cast<unsigned long long*>(g_W2v)[t] = v;
}

// ---------------- main: gather + density reduce + app GEMM (f32x2) ----------------
__global__ __launch_bounds__(128, 3)
void tensorf_main(const float* __restrict__ xyz,
                  float* __restrict__ outSigma,
                  float* __restrict__ outApp,
                  int N) {
    extern __shared__ float smemV[];     // [128][ROWPAD]
    const int tid  = threadIdx.x;
    const int lane = tid & 31;
    const int w    = tid >> 5;
    const int blockStart = blockIdx.x * 128;
    const int sbase = blockStart + w * 32;

    // ---- Phase 1: warp-cooperative gather (lane = channel), 32 samples/warp ----
    if (sbase < N) {
        int n0 = sbase + lane;
        float mx = 0.f, my = 0.f, mz = 0.f;
        if (n0 < N) {
            mx = xyz[(size_t)n0 * 3 + 0];
            my = xyz[(size_t)n0 * 3 + 1];
            mz = xyz[(size_t)n0 * 3 + 2];
        }
#pragma unroll 2
        for (int s = 0; s < 32; s++) {
            int n = sbase + s;
            float X = __shfl_sync(0xFFFFFFFFu, mx, s);
            float Y = __shfl_sync(0xFFFFFFFFu, my, s);
            float Z = __shfl_sync(0xFFFFFFFFu, mz, s);
            if (n >= N) continue;   // uniform across warp
            // MAT_MODE = [[0,1],[0,2],[1,2]], VEC_MODE = [2,1,0]
            float cs0[3] = {X, X, Y};
            float cs1[3] = {Y, Z, Z};
            float csv[3] = {Z, Y, X};
            float dens = 0.f;
            float* vrow = smemV + (w * 32 + s) * ROWPAD;
#pragma unroll
            for (int i = 0; i < 3; i++) {
                // ---- plane bilinear (align_corners=True, zero pad) ----
                float ix = (cs0[i] + 1.f) * 149.5f;
                float iy = (cs1[i] + 1.f) * 149.5f;
                float fx = floorf(ix), fy = floorf(iy);
                float wx = ix - fx, wy = iy - fy;
                int xi = (int)fx, yi = (int)fy;
                float w1x = (xi + 1 >= 0 && xi + 1 < RES) ? wx : 0.f;
                float w0x = (xi >= 0 && xi < RES) ? (1.f - wx) : 0.f;
                float w1y = (yi + 1 >= 0 && yi + 1 < RES) ? wy : 0.f;
                float w0y = (yi >= 0 && yi < RES) ? (1.f - wy) : 0.f;
                int x0c = min(max(xi, 0), RES - 1), x1c = min(max(xi + 1, 0), RES - 1);
                int y0c = min(max(yi, 0), RES - 1), y1c = min(max(yi + 1, 0), RES - 1);
                const float* pb  = g_planeT + (size_t)i * RES * RES * NCH;
                const float* p00 = pb + (y0c * RES + x0c) * NCH;
                const float* p01 = pb + (y0c * RES + x1c) * NCH;
                const float* p10 = pb + (y1c * RES + x0c) * NCH;
                const float* p11 = pb + (y1c * RES + x1c) * NCH;
                float w00 = w0x * w0y, w01 = w1x * w0y, w10 = w0x * w1y, w11 = w1x * w1y;
                float a00 = p00[lane],      a01 = p01[lane],      a10 = p10[lane],      a11 = p11[lane];
                float b00 = p00[lane + 32], b01 = p01[lane + 32], b10 = p10[lane + 32], b11 = p11[lane + 32];
                // ---- line 1-D interp ----
                float iv = (csv[i] + 1.f) * 149.5f;
                float fv = floorf(iv);
                float wv = iv - fv;
                int vi = (int)fv;
                float wv1 = (vi + 1 >= 0 && vi + 1 < RES) ? wv : 0.f;
                float wv0 = (vi >= 0 && vi < RES) ? (1.f - wv) : 0.f;
                int v0c = min(max(vi, 0), RES - 1), v1c = min(max(vi + 1, 0), RES - 1);
                const float* l0 = g_lineT + (i * RES + v0c) * NCH;
                const float* l1 = g_lineT + (i * RES + v1c) * NCH;
                float lf0 = wv0 * l0[lane]      + wv1 * l1[lane];
                float lf1 = wv0 * l0[lane + 32] + wv1 * l1[lane + 32];

                float f0 = w00 * a00 + w01 * a01 + w10 * a10 + w11 * a11;
                float f1 = w00 * b00 + w01 * b01 + w10 * b10 + w11 * b11;
                float p0 = f0 * lf0;             // channel c = lane       (app)
                float p1 = f1 * lf1;             // channel c = lane + 32
                vrow[i * NC_A + lane] = p0;
                if (lane < 16) vrow[i * NC_A + 32 + lane] = p1;   // app ch 32..47
                else           dens += p1;                        // density ch 48..63
            }
            // reduce density over lanes 16..31 (closed under xor<16)
            dens += __shfl_xor_sync(0xFFFFFFFFu, dens, 1);
            dens += __shfl_xor_sync(0xFFFFFFFFu, dens, 2);
            dens += __shfl_xor_sync(0xFFFFFFFFu, dens, 4);
            dens += __shfl_xor_sync(0xFFFFFFFFu, dens, 8);
            if (lane == 16) outSigma[n] = dens;
        }
    }
    __syncwarp();

    // ---- Phase 2: per-thread app GEMM via packed f32x2 FMA (W pairs in constant) ----
    {
        int n = blockStart + tid;     // == sbase + lane
        unsigned long long acc[NPAIR] = {0ull};
        if (n < N) {
            const float* row = smemV + tid * ROWPAD;
#pragma unroll 2
            for (int k4 = 0; k4 < KDIM; k4 += 4) {
                float4 v4 = *reinterpret_cast<const float4*>(row + k4);
                float vv[4] = {v4.x, v4.y, v4.z, v4.w};
#pragma unroll
                for (int j = 0; j < 4; j++) {
                    unsigned long long a2;
                    asm("mov.b64 %0, {%1, %1};" : "=l"(a2) : "r"(__float_as_uint(vv[j])));
                    int k = k4 + j;
#pragma unroll
                    for (int q = 0; q < NPAIR / 2; q++) {
                        ulonglong2 w2 = c_W2v[k * (NPAIR / 2) + q];
                        asm("fma.rn.f32x2 %0, %1, %2, %0;" : "+l"(acc[2 * q])     : "l"(a2), "l"(w2.x));
                        asm("fma.rn.f32x2 %0, %1, %2, %0;" : "+l"(acc[2 * q + 1]) : "l"(a2), "l"(w2.y));
                    }
                }
            }
            // stash this thread's 27 outputs into its own smem row (reuse)
            float* rw = smemV + tid * ROWPAD;
#pragma unroll
            for (int jj = 0; jj < NPAIR; jj++) {
                unsigned int lo, hi;
                asm("mov.b64 {%0, %1}, %2;" : "=r"(lo), "=r"(hi) : "l"(acc[jj]));
                rw[2 * jj] = __uint_as_float(lo);
                if (2 * jj + 1 < APP_DIM) rw[2 * jj + 1] = __uint_as_float(hi);
            }
        }
        __syncwarp();
        // warp-cooperative coalesced store of this warp's 32x27 app features
        if (sbase < N) {
            int cnt = min(32, N - sbase) * APP_DIM;
            size_t obase = (size_t)sbase * APP_DIM;
            for (int idx = lane; idx < cnt; idx += 32) {
                int s = idx / APP_DIM;
                int d = idx - s * APP_DIM;
                outApp[obase + idx] = smemV[(w * 32 + s) * ROWPAD + d];
            }
        }
    }
}

extern "C" void kernel_launch(void* const* d_in, const int* in_sizes, int n_in,
                              void* d_out, int out_size) {
    const float* xyz   = (const float*)d_in[0];
    const float* plane = (const float*)d_in[1];
    const float* line  = (const float*)d_in[2];
    const float* W     = (const float*)d_in[3];
    int N = in_sizes[0] / 3;

    float* outSigma = (float*)d_out;
    float* outApp   = outSigma + N;

    (void)cudaFuncSetAttribute(tensorf_main,
                               cudaFuncAttributeMaxDynamicSharedMemorySize,
                               128 * ROWPAD * sizeof(float));

    // pack W on-device, then copy into constant bank (D2D, capturable)
    pack_W_k<<<(KDIM * NPAIR + 255) / 256, 256>>>(W);
    void* w2addr = nullptr;
    cudaGetSymbolAddress(&w2addr, g_W2v);
    cudaMemcpyToSymbolAsync(c_W2v, w2addr, sizeof(ulonglong2) * (KDIM * NPAIR / 2), 0,
                            cudaMemcpyDeviceToDevice, 0);

    transpose_planes_k<<<dim3((RES + 31) / 32, NCH / 32, 3 * RES), dim3(32, 8)>>>(plane);
    transpose_lines_k<<<(3 * RES * NCH + 255) / 256, 256>>>(line);

    int grid = (N + 127) / 128;
    tensorf_main<<<grid, 128, 128 * ROWPAD * sizeof(float)>>>(xyz, outSigma, outApp, N);
}

// round 6
// speedup vs baseline: 1.6450x; 1.0884x over previous
#include <cuda_runtime.h>
#include <cuda_bf16.h>

#define RES 300
#define NCH 64            // NC_A + NC_D
#define NC_A 48
#define APP_DIM 27
#define KDIM (3*NC_A)     // 144
#define NPAIR 14          // ceil(27/2)
#define ROWS 52           // smem row stride in floats (52 mod 32 = 20 -> conflict-free ld.128)

// Scratch: transposed planes [3][y][x][c] and lines [3][y][c]
__device__ float g_planeT[3 * RES * RES * NCH];           // 69.1 MB
__device__ float g_lineT[3 * RES * NCH];                  // 230 KB
__device__ ulonglong2 g_W2v[KDIM * NPAIR / 2];            // packed W staging
__constant__ ulonglong2 c_W2v[KDIM * NPAIR / 2];          // [k][7] of 2x f32x2 pairs

// ---------------- transpose planes: (3,64,300,300) -> [3][y][x][64] ----------------
__global__ void transpose_planes_k(const float* __restrict__ in) {
    __shared__ float tile[32][33];
    int iy = blockIdx.z;                 // i*RES + y
    int i = iy / RES, y = iy - i * RES;
    int x0 = blockIdx.x * 32, c0 = blockIdx.y * 32;
#pragma unroll
    for (int j = 0; j < 4; j++) {
        int c = c0 + threadIdx.y + j * 8;
        int x = x0 + threadIdx.x;
        float v = 0.f;
        if (x < RES) v = in[((i * NCH + c) * RES + y) * RES + x];   // coalesced in x
        tile[threadIdx.y + j * 8][threadIdx.x] = v;
    }
    __syncthreads();
#pragma unroll
    for (int j = 0; j < 4; j++) {
        int x = x0 + threadIdx.y + j * 8;
        int c = c0 + threadIdx.x;
        if (x < RES)                                                 // coalesced in c
            g_planeT[((i * RES + y) * RES + x) * NCH + c] = tile[threadIdx.x][threadIdx.y + j * 8];
    }
}

// ---------------- transpose lines: (3,64,300,1) -> [3][y][64] ----------------
__global__ void transpose_lines_k(const float* __restrict__ in) {
    int t = blockIdx.x * 256 + threadIdx.x;
    if (t >= 3 * RES * NCH) return;
    int c = t & 63;
    int rest = t >> 6;
    int y = rest % RES;
    int i = rest / RES;
    g_lineT[t] = in[(i * NCH + c) * RES + y];
}

// ---------------- pack basis_W: [27][144] -> k-major f32x2 pairs ----------------
__global__ void pack_W_k(const float* __restrict__ W) {
    int t = blockIdx.x * 256 + threadIdx.x;       // over KDIM*NPAIR = 2016
    if (t >= KDIM * NPAIR) return;
    int k = t / NPAIR, jj = t - k * NPAIR;
    int d0 = 2 * jj, d1 = 2 * jj + 1;
    float lo = W[d0 * KDIM + k];
    float hi = (d1 < APP_DIM) ? W[d1 * KDIM + k] : 0.f;
    unsigned long long v = ((unsigned long long)__float_as_uint(hi) << 32)
                         | (unsigned long long)__float_as_uint(lo);
    reinterpret_cast<unsigned long long*>(g_W2v)[t] = v;
}

// ---------------- main: i-outer gather + chunked f32x2 GEMM ----------------
__global__ __launch_bounds__(128, 6)
void tensorf_main(const float* __restrict__ xyz,
                  float* __restrict__ outSigma,
                  float* __restrict__ outApp,
                  int N) {
    __shared__ float smemV[128 * ROWS];   // 26.6 KB: per-sample 48-ch chunk
    __shared__ float smemD[128];          // per-sample density partial
    const int tid  = threadIdx.x;
    const int lane = tid & 31;
    const int w    = tid >> 5;
    const int blockStart = blockIdx.x * 128;
    const int sbase = blockStart + w * 32;
    const int nT = blockStart + tid;
    const int scount = min(32, N - sbase);   // warp-uniform samples in this warp

    // per-lane sample coords (clamped load; unused tails never consumed)
    float mx, my, mz;
    {
        int n0 = min(sbase + lane, N - 1);
        mx = xyz[(size_t)n0 * 3 + 0];
        my = xyz[(size_t)n0 * 3 + 1];
        mz = xyz[(size_t)n0 * 3 + 2];
    }

    unsigned long long acc[NPAIR];
#pragma unroll
    for (int q = 0; q < NPAIR; q++) acc[q] = 0ull;

#pragma unroll
    for (int i = 0; i < 3; i++) {
        const float* pb = g_planeT + (size_t)i * RES * RES * NCH;
        const float* lb = g_lineT + i * RES * NCH;

        // ---- gather this plane's 48 app channels for scount samples (warp-coop) ----
        for (int s = 0; s < scount; s++) {
            float X = __shfl_sync(0xFFFFFFFFu, mx, s);
            float Y = __shfl_sync(0xFFFFFFFFu, my, s);
            float Z = __shfl_sync(0xFFFFFFFFu, mz, s);
            // MAT_MODE = [[0,1],[0,2],[1,2]], VEC_MODE = [2,1,0]
            float c0 = (i == 2) ? Y : X;
            float c1 = (i == 0) ? Y : Z;
            float cv = (i == 0) ? Z : ((i == 1) ? Y : X);

            // plane bilinear (coords guaranteed in [-1,1] -> ix,iy in [0,299])
            float ix = fmaf(c0, 149.5f, 149.5f);
            float iy = fmaf(c1, 149.5f, 149.5f);
            int xi = (int)ix, yi = (int)iy;       // trunc == floor (nonneg)
            float wx = ix - (float)xi, wy = iy - (float)yi;
            int x1 = min(xi + 1, RES - 1), y1 = min(yi + 1, RES - 1);
            const float* r0 = pb + (yi * RES + xi) * NCH;
            const float* r1 = pb + (y1 * RES + xi) * NCH;
            int dx = (x1 - xi) * NCH;             // 0 or 64 floats
            float a00 = r0[lane],      a01 = r0[dx + lane];
            float a10 = r1[lane],      a11 = r1[dx + lane];
            float b00 = r0[lane + 32], b01 = r0[dx + lane + 32];
            float b10 = r1[lane + 32], b11 = r1[dx + lane + 32];
            float w0x = 1.f - wx, w0y = 1.f - wy;
            float w00 = w0x * w0y, w01 = wx * w0y, w10 = w0x * wy, w11 = wx * wy;
            float f0 = fmaf(a00, w00, fmaf(a01, w01, fmaf(a10, w10, a11 * w11)));
            float f1 = fmaf(b00, w00, fmaf(b01, w01, fmaf(b10, w10, b11 * w11)));

            // line 1-D interp
            float iv = fmaf(cv, 149.5f, 149.5f);
            int vi = (int)iv;
            float wv = iv - (float)vi;
            int v1 = min(vi + 1, RES - 1);
            const float* l0 = lb + vi * NCH;
            const float* l1 = lb + v1 * NCH;
            float wv0 = 1.f - wv;
            float lf0 = fmaf(l0[lane], wv0, l1[lane] * wv);
            float lf1 = fmaf(l0[lane + 32], wv0, l1[lane + 32] * wv);

            float p0 = f0 * lf0;                  // app channel lane (0..31)
            float p1 = f1 * lf1;                  // channel lane+32
            int row = w * 32 + s;
            smemV[row * ROWS + lane] = p0;
            if (lane < 16) smemV[row * ROWS + 32 + lane] = p1;   // app ch 32..47
            float d = (lane >= 16) ? p1 : 0.f;                   // density ch 48..63
            d += __shfl_xor_sync(0xFFFFFFFFu, d, 8);
            d += __shfl_xor_sync(0xFFFFFFFFu, d, 4);
            d += __shfl_xor_sync(0xFFFFFFFFu, d, 2);
            d += __shfl_xor_sync(0xFFFFFFFFu, d, 1);
            if (lane == 16) {
                if (i == 0) smemD[row] = d; else smemD[row] += d;
            }
        }
        __syncwarp();

        // ---- accumulate this 48-chunk into app accumulators (thread = sample) ----
        if (nT < N) {
            const float* rowp = smemV + tid * ROWS;
#pragma unroll 2
            for (int k4 = 0; k4 < NC_A; k4 += 4) {
                float4 v4 = *reinterpret_cast<const float4*>(rowp + k4);
                float vv[4] = {v4.x, v4.y, v4.z, v4.w};
#pragma unroll
                for (int j = 0; j < 4; j++) {
                    unsigned long long a2;
                    asm("mov.b64 %0, {%1, %1};" : "=l"(a2) : "r"(__float_as_uint(vv[j])));
                    int k = i * NC_A + k4 + j;
#pragma unroll
                    for (int q = 0; q < NPAIR / 2; q++) {
                        ulonglong2 w2 = c_W2v[k * (NPAIR / 2) + q];
                        asm("fma.rn.f32x2 %0, %1, %2, %0;" : "+l"(acc[2 * q])     : "l"(a2), "l"(w2.x));
                        asm("fma.rn.f32x2 %0, %1, %2, %0;" : "+l"(acc[2 * q + 1]) : "l"(a2), "l"(w2.y));
                    }
                }
            }
        }
        __syncwarp();   // GEMM chunk done before next i overwrites rows (same warp)
    }

    // ---- epilogue: sigma + staged coalesced app store ----
    if (nT < N) {
        float* rw = smemV + tid * ROWS;
#pragma unroll
        for (int jj = 0; jj < NPAIR; jj++) {
            unsigned int lo, hi;
            asm("mov.b64 {%0, %1}, %2;" : "=r"(lo), "=r"(hi) : "l"(acc[jj]));
            rw[2 * jj] = __uint_as_float(lo);
            if (2 * jj + 1 < APP_DIM) rw[2 * jj + 1] = __uint_as_float(hi);
        }
        outSigma[nT] = smemD[tid];
    }
    __syncwarp();
    if (scount > 0) {
        int cnt = scount * APP_DIM;
        size_t obase = (size_t)sbase * APP_DIM;
        for (int idx = lane; idx < cnt; idx += 32) {
            int s2 = idx / APP_DIM;
            int d2 = idx - s2 * APP_DIM;
            outApp[obase + idx] = smemV[(w * 32 + s2) * ROWS + d2];
        }
    }
}

extern "C" void kernel_launch(void* const* d_in, const int* in_sizes, int n_in,
                              void* d_out, int out_size) {
    const float* xyz   = (const float*)d_in[0];
    const float* plane = (const float*)d_in[1];
    const float* line  = (const float*)d_in[2];
    const float* W     = (const float*)d_in[3];
    int N = in_sizes[0] / 3;

    float* outSigma = (float*)d_out;
    float* outApp   = outSigma + N;

    // pack W on-device, then copy into constant bank (D2D, capturable)
    pack_W_k<<<(KDIM * NPAIR + 255) / 256, 256>>>(W);
    void* w2addr = nullptr;
    cudaGetSymbolAddress(&w2addr, g_W2v);
    cudaMemcpyToSymbolAsync(c_W2v, w2addr, sizeof(ulonglong2) * (KDIM * NPAIR / 2), 0,
                            cudaMemcpyDeviceToDevice, 0);

    transpose_planes_k<<<dim3((RES + 31) / 32, NCH / 32, 3 * RES), dim3(32, 8)>>>(plane);
    transpose_lines_k<<<(3 * RES * NCH + 255) / 256, 256>>>(line);

    int grid = (N + 127) / 128;
    tensorf_main<<<grid, 128>>>(xyz, outSigma, outApp, N);
}

// round 7
// speedup vs baseline: 2.1794x; 1.3249x over previous
#include <cuda_runtime.h>
#include <cuda_bf16.h>

#define RES 300
#define NCH 64            // NC_A + NC_D
#define NC_A 48
#define APP_DIM 27
#define KDIM (3*NC_A)     // 144
#define NPAIR 14          // ceil(27/2)
#define NW2 (KDIM*NPAIR/2)// 1008 ulonglong2 entries of packed W
#define ROWS 52           // smem row stride in floats (conflict-free for ld.128)

// Scratch: transposed planes [3][y][x][32 float2 pairs] and lines [3][y][32 pairs]
__device__ float g_planeT[3 * RES * RES * NCH];           // 69.1 MB (float2-paired)
__device__ float g_lineT[3 * RES * NCH];                  // 230 KB (float2-paired)
__device__ ulonglong2 g_W2v[NW2];                         // packed W: [k][7] of 2x f32x2 pairs

// ---------------- transpose planes: (3,64,300,300) -> [3][y][x][pair(c,c+32)] ----------------
__global__ void transpose_planes_k(const float* __restrict__ in) {
    __shared__ float tile[64][33];
    int iy = blockIdx.z;                 // i*RES + y
    int i = iy / RES, y = iy - i * RES;
    int x0 = blockIdx.x * 32;
    int tx = threadIdx.x, ty = threadIdx.y;
#pragma unroll
    for (int j = 0; j < 8; j++) {
        int c = ty + j * 8;
        int x = x0 + tx;
        float v = 0.f;
        if (x < RES) v = in[((i * NCH + c) * RES + y) * RES + x];   // coalesced in x
        tile[c][tx] = v;
    }
    __syncthreads();
    float2* out = reinterpret_cast<float2*>(g_planeT);
#pragma unroll
    for (int j = 0; j < 4; j++) {
        int xl = ty + j * 8;
        int x = x0 + xl;
        if (x < RES) {
            float2 v;
            v.x = tile[tx][xl];
            v.y = tile[tx + 32][xl];
            out[((size_t)(i * RES + y) * RES + x) * 32 + tx] = v;   // 256B coalesced
        }
    }
}

// ---------------- transpose lines: (3,64,300,1) -> [3][y][pair(c,c+32)] ----------------
__global__ void transpose_lines_k(const float* __restrict__ in) {
    int t = blockIdx.x * 256 + threadIdx.x;
    if (t >= 3 * RES * 32) return;
    int p = t & 31;
    int rest = t >> 5;
    int y = rest % RES;
    int i = rest / RES;
    float2 v;
    v.x = in[(i * NCH + p) * RES + y];
    v.y = in[(i * NCH + p + 32) * RES + y];
    reinterpret_cast<float2*>(g_lineT)[t] = v;
}

// ---------------- pack basis_W: [27][144] -> k-major f32x2 pairs ----------------
__global__ void pack_W_k(const float* __restrict__ W) {
    int t = blockIdx.x * 256 + threadIdx.x;       // over KDIM*NPAIR = 2016
    if (t >= KDIM * NPAIR) return;
    int k = t / NPAIR, jj = t - k * NPAIR;
    int d0 = 2 * jj, d1 = 2 * jj + 1;
    float lo = W[d0 * KDIM + k];
    float hi = (d1 < APP_DIM) ? W[d1 * KDIM + k] : 0.f;
    unsigned long long v = ((unsigned long long)__float_as_uint(hi) << 32)
                         | (unsigned long long)__float_as_uint(lo);
    reinterpret_cast<unsigned long long*>(g_W2v)[t] = v;
}

// ---------------- main: i-outer paired gather + chunked f32x2 GEMM (W in smem) ----------------
__global__ __launch_bounds__(128, 5)
void tensorf_main(const float* __restrict__ xyz,
                  float* __restrict__ outSigma,
                  float* __restrict__ outApp,
                  int N) {
    __shared__ float smemV[128 * ROWS];       // 26.6 KB: per-sample 48-ch chunk
    __shared__ float smemD[128];              // per-sample density partial
    __shared__ ulonglong2 smemW[NW2];         // 16.1 KB packed W (broadcast LDS)
    const int tid  = threadIdx.x;
    const int lane = tid & 31;
    const int w    = tid >> 5;
    const int blockStart = blockIdx.x * 128;
    const int sbase = blockStart + w * 32;
    const int nT = blockStart + tid;
    const int scount = min(32, N - sbase);    // warp-uniform samples in this warp

    // stage packed W into smem (read via uniform-address broadcast later)
#pragma unroll
    for (int t = 0; t < NW2; t += 128) {
        int idx = t + tid;
        if (idx < NW2) smemW[idx] = g_W2v[idx];
    }

    // per-lane sample coords (clamped load; unused tails never consumed)
    float mx, my, mz;
    {
        int n0 = min(sbase + lane, N - 1);
        mx = xyz[(size_t)n0 * 3 + 0];
        my = xyz[(size_t)n0 * 3 + 1];
        mz = xyz[(size_t)n0 * 3 + 2];
    }
    __syncthreads();   // W staged before any warp reaches its GEMM phase

    unsigned long long acc[NPAIR];
#pragma unroll
    for (int q = 0; q < NPAIR; q++) acc[q] = 0ull;

#pragma unroll
    for (int i = 0; i < 3; i++) {
        const float2* pb = reinterpret_cast<const float2*>(g_planeT) + (size_t)i * RES * RES * 32;
        const float2* lb = reinterpret_cast<const float2*>(g_lineT) + i * RES * 32;

        // ---- gather this plane's channels for scount samples (warp-coop, float2 lanes) ----
#pragma unroll 2
        for (int s = 0; s < scount; s++) {
            float X = __shfl_sync(0xFFFFFFFFu, mx, s);
            float Y = __shfl_sync(0xFFFFFFFFu, my, s);
            float Z = __shfl_sync(0xFFFFFFFFu, mz, s);
            // MAT_MODE = [[0,1],[0,2],[1,2]], VEC_MODE = [2,1,0]
            float c0 = (i == 2) ? Y : X;
            float c1 = (i == 0) ? Y : Z;
            float cv = (i == 0) ? Z : ((i == 1) ? Y : X);

            // plane bilinear (coords in [-1,1] -> ix,iy in [0,299])
            float ix = fmaf(c0, 149.5f, 149.5f);
            float iy = fmaf(c1, 149.5f, 149.5f);
            int xi = (int)ix, yi = (int)iy;       // trunc == floor (nonneg)
            float wx = ix - (float)xi, wy = iy - (float)yi;
            int x1 = min(xi + 1, RES - 1), y1 = min(yi + 1, RES - 1);
            const float2* r0 = pb + (yi * RES + xi) * 32;
            const float2* r1 = pb + (y1 * RES + xi) * 32;
            int dx = (x1 - xi) * 32;              // 0 or 32 float2
            float2 A00 = r0[lane],      A01 = r0[dx + lane];
            float2 A10 = r1[lane],      A11 = r1[dx + lane];
            float w0x = 1.f - wx, w0y = 1.f - wy;
            float w00 = w0x * w0y, w01 = wx * w0y, w10 = w0x * wy, w11 = wx * wy;
            float f0 = fmaf(A00.x, w00, fmaf(A01.x, w01, fmaf(A10.x, w10, A11.x * w11)));
            float f1 = fmaf(A00.y, w00, fmaf(A01.y, w01, fmaf(A10.y, w10, A11.y * w11)));

            // line 1-D interp
            float iv = fmaf(cv, 149.5f, 149.5f);
            int vi = (int)iv;
            float wv = iv - (float)vi;
            int v1 = min(vi + 1, RES - 1);
            float2 L0 = lb[vi * 32 + lane];
            float2 L1 = lb[v1 * 32 + lane];
            float wv0 = 1.f - wv;
            float lf0 = fmaf(L0.x, wv0, L1.x * wv);
            float lf1 = fmaf(L0.y, wv0, L1.y * wv);

            float p0 = f0 * lf0;                  // app channel lane (0..31)
            float p1 = f1 * lf1;                  // channel lane+32
            int row = w * 32 + s;
            smemV[row * ROWS + lane] = p0;
            if (lane < 16) smemV[row * ROWS + 32 + lane] = p1;   // app ch 32..47
            float d = (lane >= 16) ? p1 : 0.f;                   // density ch 48..63
            d += __shfl_xor_sync(0xFFFFFFFFu, d, 8);
            d += __shfl_xor_sync(0xFFFFFFFFu, d, 4);
            d += __shfl_xor_sync(0xFFFFFFFFu, d, 2);
            d += __shfl_xor_sync(0xFFFFFFFFu, d, 1);
            if (lane == 16) {
                if (i == 0) smemD[row] = d; else smemD[row] += d;
            }
        }
        __syncwarp();

        // ---- accumulate this 48-chunk into app accumulators (thread = sample) ----
        if (nT < N) {
            const float* rowp = smemV + tid * ROWS;
#pragma unroll 2
            for (int k4 = 0; k4 < NC_A; k4 += 4) {
                float4 v4 = *reinterpret_cast<const float4*>(rowp + k4);
                float vv[4] = {v4.x, v4.y, v4.z, v4.w};
#pragma unroll
                for (int j = 0; j < 4; j++) {
                    unsigned long long a2;
                    asm("mov.b64 %0, {%1, %1};" : "=l"(a2) : "r"(__float_as_uint(vv[j])));
                    int k = i * NC_A + k4 + j;
#pragma unroll
                    for (int q = 0; q < NPAIR / 2; q++) {
                        ulonglong2 w2 = smemW[k * (NPAIR / 2) + q];   // uniform addr -> LDS broadcast
                        asm("fma.rn.f32x2 %0, %1, %2, %0;" : "+l"(acc[2 * q])     : "l"(a2), "l"(w2.x));
                        asm("fma.rn.f32x2 %0, %1, %2, %0;" : "+l"(acc[2 * q + 1]) : "l"(a2), "l"(w2.y));
                    }
                }
            }
        }
        __syncwarp();   // GEMM chunk done before next i overwrites rows (same warp)
    }

    // ---- epilogue: sigma + staged coalesced app store ----
    if (nT < N) {
        float* rw = smemV + tid * ROWS;
#pragma unroll
        for (int jj = 0; jj < NPAIR; jj++) {
            unsigned int lo, hi;
            asm("mov.b64 {%0, %1}, %2;" : "=r"(lo), "=r"(hi) : "l"(acc[jj]));
            rw[2 * jj] = __uint_as_float(lo);
            if (2 * jj + 1 < APP_DIM) rw[2 * jj + 1] = __uint_as_float(hi);
        }
        outSigma[nT] = smemD[tid];
    }
    __syncwarp();
    if (scount > 0) {
        int cnt = scount * APP_DIM;
        size_t obase = (size_t)sbase * APP_DIM;
        for (int idx = lane; idx < cnt; idx += 32) {
            int s2 = idx / APP_DIM;
            int d2 = idx - s2 * APP_DIM;
            outApp[obase + idx] = smemV[(w * 32 + s2) * ROWS + d2];
        }
    }
}

extern "C" void kernel_launch(void* const* d_in, const int* in_sizes, int n_in,
                              void* d_out, int out_size) {
    const float* xyz   = (const float*)d_in[0];
    const float* plane = (const float*)d_in[1];
    const float* line  = (const float*)d_in[2];
    const float* W     = (const float*)d_in[3];
    int N = in_sizes[0] / 3;

    float* outSigma = (float*)d_out;
    float* outApp   = outSigma + N;

    pack_W_k<<<(KDIM * NPAIR + 255) / 256, 256>>>(W);
    transpose_planes_k<<<dim3((RES + 31) / 32, 1, 3 * RES), dim3(32, 8)>>>(plane);
    transpose_lines_k<<<(3 * RES * 32 + 255) / 256, 256>>>(line);

    int grid = (N + 127) / 128;
    tensorf_main<<<grid, 128>>>(xyz, outSigma, outApp, N);
}

// round 9
// speedup vs baseline: 2.2176x; 1.0175x over previous
#include <cuda_runtime.h>
#include <cuda_bf16.h>

#define RES 300
#define NCH 64            // NC_A + NC_D
#define NC_A 48
#define APP_DIM 27
#define KDIM (3*NC_A)     // 144
#define NPAIR 14          // ceil(27/2)
#define NW2 (KDIM*NPAIR/2)// 1008 ulonglong2 entries of packed W
#define ROWS 52           // smem row stride in floats (16B-aligned rows, conflict-free ld.128)

// Scratch: transposed planes [3][y][x][64] and lines [3][y][64]
__device__ float g_planeT[3 * RES * RES * NCH];           // 69.1 MB
__device__ float g_lineT[3 * RES * NCH];                  // 230 KB
__device__ ulonglong2 g_W2v[NW2];                         // packed W: [k][7] of 2x f32x2 pairs

// ---------------- transpose planes: (3,64,300,300) -> [3][y][x][64] ----------------
__global__ void transpose_planes_k(const float* __restrict__ in) {
    __shared__ float tile[32][33];
    int iy = blockIdx.z;                 // i*RES + y
    int i = iy / RES, y = iy - i * RES;
    int x0 = blockIdx.x * 32, c0 = blockIdx.y * 32;
#pragma unroll
    for (int j = 0; j < 4; j++) {
        int c = c0 + threadIdx.y + j * 8;
        int x = x0 + threadIdx.x;
        float v = 0.f;
        if (x < RES) v = in[((i * NCH + c) * RES + y) * RES + x];   // coalesced in x
        tile[threadIdx.y + j * 8][threadIdx.x] = v;
    }
    __syncthreads();
#pragma unroll
    for (int j = 0; j < 4; j++) {
        int x = x0 + threadIdx.y + j * 8;
        int c = c0 + threadIdx.x;
        if (x < RES)                                                 // coalesced in c
            g_planeT[((size_t)(i * RES + y) * RES + x) * NCH + c] = tile[threadIdx.x][threadIdx.y + j * 8];
    }
}

// ---------------- transpose lines: (3,64,300,1) -> [3][y][64] ----------------
__global__ void transpose_lines_k(const float* __restrict__ in) {
    int t = blockIdx.x * 256 + threadIdx.x;
    if (t >= 3 * RES * NCH) return;
    int c = t & 63;
    int rest = t >> 6;
    int y = rest % RES;
    int i = rest / RES;
    g_lineT[t] = in[(i * NCH + c) * RES + y];
}

// ---------------- pack basis_W: [27][144] -> k-major f32x2 pairs ----------------
__global__ void pack_W_k(const float* __restrict__ W) {
    int t = blockIdx.x * 256 + threadIdx.x;       // over KDIM*NPAIR = 2016
    if (t >= KDIM * NPAIR) return;
    int k = t / NPAIR, jj = t - k * NPAIR;
    int d0 = 2 * jj, d1 = 2 * jj + 1;
    float lo = W[d0 * KDIM + k];
    float hi = (d1 < APP_DIM) ? W[d1 * KDIM + k] : 0.f;
    unsigned long long v = ((unsigned long long)__float_as_uint(hi) << 32)
                         | (unsigned long long)__float_as_uint(lo);
    reinterpret_cast<unsigned long long*>(g_W2v)[t] = v;
}

// ---------------- main: half-warp float4 gather + chunked f32x2 GEMM (W in smem) ----------------
__global__ __launch_bounds__(128, 5)
void tensorf_main(const float* __restrict__ xyz,
                  float* __restrict__ outSigma,
                  float* __restrict__ outApp,
                  int N) {
    __shared__ float smemV[128 * ROWS];       // 26.6 KB: per-sample 48-ch chunk
    __shared__ float smemD[128];              // per-sample density partial
    __shared__ ulonglong2 smemW[NW2];         // 16.1 KB packed W (broadcast LDS)
    const int tid  = threadIdx.x;
    const int lane = tid & 31;
    const int w    = tid >> 5;
    const int half = lane >> 4;               // half-warp id (0/1)
    const int lq   = lane & 15;               // lane within half: 4-channel group index
    const int blockStart = blockIdx.x * 128;
    const int sbase = blockStart + w * 32;
    const int nT = blockStart + tid;
    const int scount = min(32, N - sbase);     // warp-uniform samples in this warp

    // stage packed W into smem
#pragma unroll
    for (int t = 0; t < NW2; t += 128) {
        int idx = t + tid;
        if (idx < NW2) smemW[idx] = g_W2v[idx];
    }

    // per-lane sample coords (clamped; garbage tails never consumed)
    float mx, my, mz;
    {
        int n0 = min(sbase + lane, N - 1);
        mx = xyz[(size_t)n0 * 3 + 0];
        my = xyz[(size_t)n0 * 3 + 1];
        mz = xyz[(size_t)n0 * 3 + 2];
    }
    __syncthreads();   // W staged before any warp reaches its GEMM phase

    unsigned long long acc[NPAIR];
#pragma unroll
    for (int q = 0; q < NPAIR; q++) acc[q] = 0ull;

#pragma unroll
    for (int i = 0; i < 3; i++) {
        const float4* pb = reinterpret_cast<const float4*>(g_planeT + (size_t)i * RES * RES * NCH);
        const float4* lb = reinterpret_cast<const float4*>(g_lineT + i * RES * NCH);

        // ---- gather: 2 samples per iteration (one per half-warp), float4 per lane ----
#pragma unroll 2
        for (int j = 0; 2 * j < scount; j++) {
            int srcl = 2 * j + half;          // sample slot handled by this half-warp
            float X = __shfl_sync(0xFFFFFFFFu, mx, srcl);
            float Y = __shfl_sync(0xFFFFFFFFu, my, srcl);
            float Z = __shfl_sync(0xFFFFFFFFu, mz, srcl);
            // MAT_MODE = [[0,1],[0,2],[1,2]], VEC_MODE = [2,1,0]
            float c0 = (i == 2) ? Y : X;
            float c1 = (i == 0) ? Y : Z;
            float cv = (i == 0) ? Z : ((i == 1) ? Y : X);

            // plane bilinear (coords in [-1,1] -> ix,iy in [0,299])
            float ix = fmaf(c0, 149.5f, 149.5f);
            float iy = fmaf(c1, 149.5f, 149.5f);
            int xi = (int)ix, yi = (int)iy;    // trunc == floor (nonneg)
            float wx = ix - (float)xi, wy = iy - (float)yi;
            int x1 = min(xi + 1, RES - 1), y1 = min(yi + 1, RES - 1);
            const float4* r0 = pb + (size_t)(yi * RES + xi) * 16 + lq;
            const float4* r1 = pb + (size_t)(y1 * RES + xi) * 16 + lq;
            int dx4 = (x1 - xi) * 16;          // 0 or 16 float4
            float4 A00 = r0[0],   A01 = r0[dx4];
            float4 A10 = r1[0],   A11 = r1[dx4];
            float w0x = 1.f - wx, w0y = 1.f - wy;
            float w00 = w0x * w0y, w01 = wx * w0y, w10 = w0x * wy, w11 = wx * wy;
            float4 f;
            f.x = fmaf(A00.x, w00, fmaf(A01.x, w01, fmaf(A10.x, w10, A11.x * w11)));
            f.y = fmaf(A00.y, w00, fmaf(A01.y, w01, fmaf(A10.y, w10, A11.y * w11)));
            f.z = fmaf(A00.z, w00, fmaf(A01.z, w01, fmaf(A10.z, w10, A11.z * w11)));
            f.w = fmaf(A00.w, w00, fmaf(A01.w, w01, fmaf(A10.w, w10, A11.w * w11)));

            // line 1-D interp
            float iv = fmaf(cv, 149.5f, 149.5f);
            int vi = (int)iv;
            float wv = iv - (float)vi;
            int v1 = min(vi + 1, RES - 1);
            float4 L0 = lb[vi * 16 + lq];
            float4 L1 = lb[v1 * 16 + lq];
            float wv0 = 1.f - wv;
            float4 p;
            p.x = f.x * fmaf(L0.x, wv0, L1.x * wv);
            p.y = f.y * fmaf(L0.y, wv0, L1.y * wv);
            p.z = f.z * fmaf(L0.z, wv0, L1.z * wv);
            p.w = f.w * fmaf(L0.w, wv0, L1.w * wv);

            int row = w * 32 + srcl;
            if (lq < 12)                        // app channels 0..47 (4 per lane)
                *reinterpret_cast<float4*>(smemV + row * ROWS + 4 * lq) = p;
            // density channels 48..63 live in lanes lq=12..15
            float d = (lq >= 12) ? (p.x + p.y + p.z + p.w) : 0.f;
            d += __shfl_xor_sync(0xFFFFFFFFu, d, 1);
            d += __shfl_xor_sync(0xFFFFFFFFu, d, 2);
            if (lq == 12) {
                if (i == 0) smemD[row] = d; else smemD[row] += d;
            }
        }
        __syncwarp();

        // ---- accumulate this 48-chunk into app accumulators (thread = sample) ----
        if (nT < N) {
            const float* rowp = smemV + tid * ROWS;
#pragma unroll 2
            for (int k4 = 0; k4 < NC_A; k4 += 4) {
                float4 v4 = *reinterpret_cast<const float4*>(rowp + k4);
                float vv[4] = {v4.x, v4.y, v4.z, v4.w};
#pragma unroll
                for (int j = 0; j < 4; j++) {
                    unsigned long long a2;
                    asm("mov.b64 %0, {%1, %1};" : "=l"(a2) : "r"(__float_as_uint(vv[j])));
                    int k = i * NC_A + k4 + j;
#pragma unroll
                    for (int q = 0; q < NPAIR / 2; q++) {
                        ulonglong2 w2 = smemW[k * (NPAIR / 2) + q];   // uniform addr -> LDS broadcast
                        asm("fma.rn.f32x2 %0, %1, %2, %0;" : "+l"(acc[2 * q])     : "l"(a2), "l"(w2.x));
                        asm("fma.rn.f32x2 %0, %1, %2, %0;" : "+l"(acc[2 * q + 1]) : "l"(a2), "l"(w2.y));
                    }
                }
            }
        }
        __syncwarp();   // GEMM chunk done before next i overwrites rows (same warp)
    }

    // ---- epilogue: sigma + staged coalesced app store ----
    if (nT < N) {
        float* rw = smemV + tid * ROWS;
#pragma unroll
        for (int jj = 0; jj < NPAIR; jj++) {
            unsigned int lo, hi;
            asm("mov.b64 {%0, %1}, %2;" : "=r"(lo), "=r"(hi) : "l"(acc[jj]));
            rw[2 * jj] = __uint_as_float(lo);
            if (2 * jj + 1 < APP_DIM) rw[2 * jj + 1] = __uint_as_float(hi);
        }
        outSigma[nT] = smemD[tid];
    }
    __syncwarp();
    if (scount > 0) {
        int cnt = scount * APP_DIM;
        size_t obase = (size_t)sbase * APP_DIM;
        for (int idx = lane; idx < cnt; idx += 32) {
            int s2 = idx / APP_DIM;
            int d2 = idx - s2 * APP_DIM;
            outApp[obase + idx] = smemV[(w * 32 + s2) * ROWS + d2];
        }
    }
}

extern "C" void kernel_launch(void* const* d_in, const int* in_sizes, int n_in,
                              void* d_out, int out_size) {
    const float* xyz   = (const float*)d_in[0];
    const float* plane = (const float*)d_in[1];
    const float* line  = (const float*)d_in[2];
    const float* W     = (const float*)d_in[3];
    int N = in_sizes[0] / 3;

    float* outSigma = (float*)d_out;
    float* outApp   = outSigma + N;

    pack_W_k<<<(KDIM * NPAIR + 255) / 256, 256>>>(W);
    transpose_planes_k<<<dim3((RES + 31) / 32, NCH / 32, 3 * RES), dim3(32, 8)>>>(plane);
    transpose_lines_k<<<(3 * RES * NCH + 255) / 256, 256>>>(line);

    int grid = (N + 127) / 128;
    tensorf_main<<<grid, 128>>>(xyz, outSigma, outApp, N);
}

// round 11
// speedup vs baseline: 3.0793x; 1.3886x over previous
#include <cuda_runtime.h>
#include <cuda_fp16.h>

#define RES 300
#define NCH 64            // NC_A + NC_D
#define NC_A 48
#define APP_DIM 27
#define KDIM (3*NC_A)     // 144
#define NPAIR 14          // ceil(27/2)
#define NW2 (KDIM*NPAIR/2)// 1008 ulonglong2 entries of packed W
#define ROWS 52           // smem row stride in floats (16B-aligned rows)

// Scratch: fp16 transposed planes [3][y][x][64] (as half2 pairs) and lines [3][y][64]
__device__ __half2 g_planeH[3 * RES * RES * 32];          // 34.6 MB
__device__ __half2 g_lineH[3 * RES * 32];                 // 115 KB
__device__ ulonglong2 g_W2v[NW2];                         // packed W: [k][7] of 2x f32x2 pairs

// ---------------- transpose planes: (3,64,300,300) -> [3][y][x][64] fp16 ----------------
__global__ void transpose_planes_k(const float* __restrict__ in) {
    __shared__ float tile[32][33];
    int iy = blockIdx.z;                 // i*RES + y
    int i = iy / RES, y = iy - i * RES;
    int x0 = blockIdx.x * 32, c0 = blockIdx.y * 32;
    int tx = threadIdx.x, ty = threadIdx.y;
#pragma unroll
    for (int j = 0; j < 4; j++) {
        int c = c0 + ty + j * 8;
        int x = x0 + tx;
        float v = 0.f;
        if (x < RES) v = in[((i * NCH + c) * RES + y) * RES + x];   // coalesced in x
        tile[ty + j * 8][tx] = v;
    }
    __syncthreads();
#pragma unroll
    for (int j = 0; j < 4; j++) {
        int xl = ty + j * 8;
        int x = x0 + xl;
        if (x < RES && tx < 16) {
            __half2 v = __floats2half2_rn(tile[2 * tx][xl], tile[2 * tx + 1][xl]);
            g_planeH[((size_t)(i * RES + y) * RES + x) * 32 + (c0 >> 1) + tx] = v;
        }
    }
}

// ---------------- transpose lines: (3,64,300,1) -> [3][y][64] fp16 ----------------
__global__ void transpose_lines_k(const float* __restrict__ in) {
    int t = blockIdx.x * 256 + threadIdx.x;
    if (t >= 3 * RES * 32) return;
    int p = t & 31;                      // half2 pair index -> channels 2p, 2p+1
    int rest = t >> 5;
    int y = rest % RES;
    int i = rest / RES;
    g_lineH[t] = __floats2half2_rn(in[(i * NCH + 2 * p) * RES + y],
                                   in[(i * NCH + 2 * p + 1) * RES + y]);
}

// ---------------- pack basis_W: [27][144] -> k-major f32x2 pairs ----------------
__global__ void pack_W_k(const float* __restrict__ W) {
    int t = blockIdx.x * 256 + threadIdx.x;       // over KDIM*NPAIR = 2016
    if (t >= KDIM * NPAIR) return;
    int k = t / NPAIR, jj = t - k * NPAIR;
    int d0 = 2 * jj, d1 = 2 * jj + 1;
    float lo = W[d0 * KDIM + k];
    float hi = (d1 < APP_DIM) ? W[d1 * KDIM + k] : 0.f;
    unsigned long long v = ((unsigned long long)__float_as_uint(hi) << 32)
                         | (unsigned long long)__float_as_uint(lo);
    reinterpret_cast<unsigned long long*>(g_W2v)[t] = v;
}

// ---------------- main: 8-lane fp16 gather + chunked f32x2 GEMM (W in smem) ----------------
__global__ __launch_bounds__(128, 5)
void tensorf_main(const float* __restrict__ xyz,
                  float* __restrict__ outSigma,
                  float* __restrict__ outApp,
                  int N) {
    __shared__ float smemV[128 * ROWS];       // 26.6 KB: per-sample 48-ch chunk
    __shared__ float smemD[128];              // per-sample density partial
    __shared__ ulonglong2 smemW[NW2];         // 16.1 KB packed W (broadcast LDS)
    const int tid  = threadIdx.x;
    const int lane = tid & 31;
    const int w    = tid >> 5;
    const int qid  = lane >> 3;               // quarter-warp id (0..3): sample slot
    const int lq   = lane & 7;                // lane in quarter: 8-channel group
    const int blockStart = blockIdx.x * 128;
    const int sbase = blockStart + w * 32;
    const int nT = blockStart + tid;
    const int scount = min(32, N - sbase);    // warp-uniform samples in this warp

    // stage packed W into smem
#pragma unroll
    for (int t = 0; t < NW2; t += 128) {
        int idx = t + tid;
        if (idx < NW2) smemW[idx] = g_W2v[idx];
    }

    // per-lane sample coords (clamped; garbage tails never consumed)
    float mx, my, mz;
    {
        int n0 = min(sbase + lane, N - 1);
        mx = xyz[(size_t)n0 * 3 + 0];
        my = xyz[(size_t)n0 * 3 + 1];
        mz = xyz[(size_t)n0 * 3 + 2];
    }
    __syncthreads();   // W staged before any warp reaches its GEMM phase

    unsigned long long acc[NPAIR];
#pragma unroll
    for (int q = 0; q < NPAIR; q++) acc[q] = 0ull;

#pragma unroll
    for (int i = 0; i < 3; i++) {
        const uint4* pb = reinterpret_cast<const uint4*>(g_planeH + (size_t)i * RES * RES * 32);
        const uint4* lb = reinterpret_cast<const uint4*>(g_lineH + i * RES * 32);

        // ---- gather: 4 samples per iteration (one per 8-lane quarter) ----
#pragma unroll 2
        for (int j = 0; 4 * j < scount; j++) {
            int srcl = 4 * j + qid;            // sample slot for this quarter
            float X = __shfl_sync(0xFFFFFFFFu, mx, srcl);
            float Y = __shfl_sync(0xFFFFFFFFu, my, srcl);
            float Z = __shfl_sync(0xFFFFFFFFu, mz, srcl);
            // MAT_MODE = [[0,1],[0,2],[1,2]], VEC_MODE = [2,1,0]
            float c0 = (i == 2) ? Y : X;
            float c1 = (i == 0) ? Y : Z;
            float cv = (i == 0) ? Z : ((i == 1) ? Y : X);

            // plane bilinear (coords in [-1,1] -> ix,iy in [0,299])
            float ix = fmaf(c0, 149.5f, 149.5f);
            float iy = fmaf(c1, 149.5f, 149.5f);
            int xi = (int)ix, yi = (int)iy;    // trunc == floor (nonneg)
            float wx = ix - (float)xi, wy = iy - (float)yi;
            int x1 = min(xi + 1, RES - 1), y1 = min(yi + 1, RES - 1);
            int b0 = (yi * RES + xi) * 8 + lq; // texel = 8 uint4
            int b1 = (y1 * RES + xi) * 8 + lq;
            int dx = (x1 - xi) * 8;            // 0 or 8 uint4
            uint4 q00 = pb[b0], q01 = pb[b0 + dx];
            uint4 q10 = pb[b1], q11 = pb[b1 + dx];

            // line 1-D interp
            float iv = fmaf(cv, 149.5f, 149.5f);
            int vi = (int)iv;
            float wv = iv - (float)vi;
            int v1 = min(vi + 1, RES - 1);
            uint4 ql0 = lb[vi * 8 + lq], ql1 = lb[v1 * 8 + lq];

            float w0x = 1.f - wx, w0y = 1.f - wy;
            float w00 = w0x * w0y, w01 = wx * w0y, w10 = w0x * wy, w11 = wx * wy;
            float wv0 = 1.f - wv;

            const __half2* h00 = reinterpret_cast<const __half2*>(&q00);
            const __half2* h01 = reinterpret_cast<const __half2*>(&q01);
            const __half2* h10 = reinterpret_cast<const __half2*>(&q10);
            const __half2* h11 = reinterpret_cast<const __half2*>(&q11);
            const __half2* hl0 = reinterpret_cast<const __half2*>(&ql0);
            const __half2* hl1 = reinterpret_cast<const __half2*>(&ql1);

            float px[8];
#pragma unroll
            for (int k = 0; k < 4; k++) {
                float2 a00 = __half22float2(h00[k]);
                float2 a01 = __half22float2(h01[k]);
                float2 a10 = __half22float2(h10[k]);
                float2 a11 = __half22float2(h11[k]);
                float2 l0  = __half22float2(hl0[k]);
                float2 l1  = __half22float2(hl1[k]);
                float fx = fmaf(a00.x, w00, fmaf(a01.x, w01, fmaf(a10.x, w10, a11.x * w11)));
                float fy = fmaf(a00.y, w00, fmaf(a01.y, w01, fmaf(a10.y, w10, a11.y * w11)));
                float lfx = fmaf(l0.x, wv0, l1.x * wv);
                float lfy = fmaf(l0.y, wv0, l1.y * wv);
                px[2 * k]     = fx * lfx;
                px[2 * k + 1] = fy * lfy;
            }

            int row = w * 32 + srcl;
            if (lq < 6) {                      // app channels 8lq..8lq+7
                float* dst = smemV + row * ROWS + 8 * lq;
                *reinterpret_cast<float4*>(dst)     = make_float4(px[0], px[1], px[2], px[3]);
                *reinterpret_cast<float4*>(dst + 4) = make_float4(px[4], px[5], px[6], px[7]);
            }
            // density channels 48..63 in lanes lq=6,7
            float d = (lq >= 6) ? (px[0] + px[1] + px[2] + px[3]
                                 + px[4] + px[5] + px[6] + px[7]) : 0.f;
            d += __shfl_xor_sync(0xFFFFFFFFu, d, 1);
            if (lq == 6) {
                if (i == 0) smemD[row] = d; else smemD[row] += d;
            }
        }
        __syncwarp();

        // ---- accumulate this 48-chunk into app accumulators (thread = sample) ----
        if (nT < N) {
            const float* rowp = smemV + tid * ROWS;
#pragma unroll 2
            for (int k4 = 0; k4 < NC_A; k4 += 4) {
                float4 v4 = *reinterpret_cast<const float4*>(rowp + k4);
                float vv[4] = {v4.x, v4.y, v4.z, v4.w};
#pragma unroll
                for (int j = 0; j < 4; j++) {
                    unsigned long long a2;
                    asm("mov.b64 %0, {%1, %1};" : "=l"(a2) : "r"(__float_as_uint(vv[j])));
                    int k = i * NC_A + k4 + j;
#pragma unroll
                    for (int q = 0; q < NPAIR / 2; q++) {
                        ulonglong2 w2 = smemW[k * (NPAIR / 2) + q];   // uniform addr -> LDS broadcast
                        asm("fma.rn.f32x2 %0, %1, %2, %0;" : "+l"(acc[2 * q])     : "l"(a2), "l"(w2.x));
                        asm("fma.rn.f32x2 %0, %1, %2, %0;" : "+l"(acc[2 * q + 1]) : "l"(a2), "l"(w2.y));
                    }
                }
            }
        }
        __syncwarp();   // GEMM chunk done before next i overwrites rows (same warp)
    }

    // ---- epilogue: sigma + staged coalesced app store ----
    if (nT < N) {
        float* rw = smemV + tid * ROWS;
#pragma unroll
        for (int jj = 0; jj < NPAIR; jj++) {
            unsigned int lo, hi;
            asm("mov.b64 {%0, %1}, %2;" : "=r"(lo), "=r"(hi) : "l"(acc[jj]));
            rw[2 * jj] = __uint_as_float(lo);
            if (2 * jj + 1 < APP_DIM) rw[2 * jj + 1] = __uint_as_float(hi);
        }
        outSigma[nT] = smemD[tid];
    }
    __syncwarp();
    if (scount > 0) {
        int cnt = scount * APP_DIM;
        size_t obase = (size_t)sbase * APP_DIM;
        for (int idx = lane; idx < cnt; idx += 32) {
            int s2 = idx / APP_DIM;
            int d2 = idx - s2 * APP_DIM;
            outApp[obase + idx] = smemV[(w * 32 + s2) * ROWS + d2];
        }
    }
}

extern "C" void kernel_launch(void* const* d_in, const int* in_sizes, int n_in,
                              void* d_out, int out_size) {
    const float* xyz   = (const float*)d_in[0];
    const float* plane = (const float*)d_in[1];
    const float* line  = (const float*)d_in[2];
    const float* W     = (const float*)d_in[3];
    int N = in_sizes[0] / 3;

    float* outSigma = (float*)d_out;
    float* outApp   = outSigma + N;

    pack_W_k<<<(KDIM * NPAIR + 255) / 256, 256>>>(W);
    transpose_planes_k<<<dim3((RES + 31) / 32, NCH / 32, 3 * RES), dim3(32, 8)>>>(plane);
    transpose_lines_k<<<(3 * RES * 32 + 255) / 256, 256>>>(line);

    int grid = (N + 127) / 128;
    tensorf_main<<<grid, 128>>>(xyz, outSigma, outApp, N);
}

// round 13
// speedup vs baseline: 3.3778x; 1.0969x over previous
#include <cuda_runtime.h>
#include <cuda_fp16.h>

#define RES 300
#define NCH 64            // NC_A + NC_D
#define NC_A 48
#define APP_DIM 27
#define KDIM (3*NC_A)     // 144
#define NPAIR 14          // ceil(27/2)
#define NW2 (KDIM*NPAIR/2)// 1008 ulonglong2 entries of packed W
#define ROWS 52           // smem row stride in floats (16B-aligned, conflict-free)

// Scratch: fp16 transposed planes [3][y][x][64] (as half2 pairs) and lines [3][y][64]
__device__ __half2 g_planeH[3 * RES * RES * 32];          // 34.6 MB
__device__ __half2 g_lineH[3 * RES * 32];                 // 115 KB
__device__ ulonglong2 g_W2v[NW2];                         // packed W: [k][7] of 2x f32x2 pairs

// ---------------- transpose planes: (3,64,300,300) -> [3][y][x][64] fp16 ----------------
__global__ void transpose_planes_k(const float* __restrict__ in) {
    __shared__ float tile[32][33];
    int iy = blockIdx.z;                 // i*RES + y
    int i = iy / RES, y = iy - i * RES;
    int x0 = blockIdx.x * 32, c0 = blockIdx.y * 32;
    int tx = threadIdx.x, ty = threadIdx.y;
#pragma unroll
    for (int j = 0; j < 4; j++) {
        int c = c0 + ty + j * 8;
        int x = x0 + tx;
        float v = 0.f;
        if (x < RES) v = in[((i * NCH + c) * RES + y) * RES + x];   // coalesced in x
        tile[ty + j * 8][tx] = v;
    }
    __syncthreads();
#pragma unroll
    for (int j = 0; j < 4; j++) {
        int xl = ty + j * 8;
        int x = x0 + xl;
        if (x < RES && tx < 16) {
            __half2 v = __floats2half2_rn(tile[2 * tx][xl], tile[2 * tx + 1][xl]);
            g_planeH[((size_t)(i * RES + y) * RES + x) * 32 + (c0 >> 1) + tx] = v;
        }
    }
}

// ---------------- transpose lines: (3,64,300,1) -> [3][y][64] fp16 ----------------
__global__ void transpose_lines_k(const float* __restrict__ in) {
    int t = blockIdx.x * 256 + threadIdx.x;
    if (t >= 3 * RES * 32) return;
    int p = t & 31;                      // half2 pair index -> channels 2p, 2p+1
    int rest = t >> 5;
    int y = rest % RES;
    int i = rest / RES;
    g_lineH[t] = __floats2half2_rn(in[(i * NCH + 2 * p) * RES + y],
                                   in[(i * NCH + 2 * p + 1) * RES + y]);
}

// ---------------- pack basis_W: [27][144] -> k-major f32x2 pairs ----------------
__global__ void pack_W_k(const float* __restrict__ W) {
    int t = blockIdx.x * 256 + threadIdx.x;       // over KDIM*NPAIR = 2016
    if (t >= KDIM * NPAIR) return;
    int k = t / NPAIR, jj = t - k * NPAIR;
    int d0 = 2 * jj, d1 = 2 * jj + 1;
    float lo = W[d0 * KDIM + k];
    float hi = (d1 < APP_DIM) ? W[d1 * KDIM + k] : 0.f;
    unsigned long long v = ((unsigned long long)__float_as_uint(hi) << 32)
                         | (unsigned long long)__float_as_uint(lo);
    reinterpret_cast<unsigned long long*>(g_W2v)[t] = v;
}

// ---------------- main: 8-lane fp16 gather + pair/half-split f32x2 GEMM ----------------
__global__ __launch_bounds__(128, 5)
void tensorf_main(const float* __restrict__ xyz,
                  float* __restrict__ outSigma,
                  float* __restrict__ outApp,
                  int N) {
    __shared__ float smemV[128 * ROWS];       // 26.6 KB: per-sample 48-ch chunk
    __shared__ float smemD[128];              // per-sample density partial
    __shared__ ulonglong2 smemW[NW2];         // 16.1 KB packed W
    const int tid  = threadIdx.x;
    const int lane = tid & 31;
    const int w    = tid >> 5;
    const int qid  = lane >> 3;               // gather: quarter-warp id (sample slot)
    const int lq   = lane & 7;                // gather: 8-channel group
    const int pr   = lane >> 1;               // GEMM: sample-pair index 0..15
    const int h    = lane & 1;                // GEMM: d-half (0: d0..15, 1: d12..27)
    const int blockStart = blockIdx.x * 128;
    const int sbase = blockStart + w * 32;
    const int scount = min(32, N - sbase);    // warp-uniform samples in this warp

    // stage packed W into smem
#pragma unroll
    for (int t = 0; t < NW2; t += 128) {
        int idx = t + tid;
        if (idx < NW2) smemW[idx] = g_W2v[idx];
    }

    // per-lane sample coords (clamped; garbage tails never consumed)
    float mx, my, mz;
    {
        int n0 = min(sbase + lane, N - 1);
        mx = xyz[(size_t)n0 * 3 + 0];
        my = xyz[(size_t)n0 * 3 + 1];
        mz = xyz[(size_t)n0 * 3 + 2];
    }
    __syncthreads();   // W staged before any warp reaches its GEMM phase

    // 2 samples x 8 f32x2 accumulators (this lane's d-half)
    unsigned long long acc[16];
#pragma unroll
    for (int q = 0; q < 16; q++) acc[q] = 0ull;

#pragma unroll
    for (int i = 0; i < 3; i++) {
        const uint4* pb = reinterpret_cast<const uint4*>(g_planeH + (size_t)i * RES * RES * 32);
        const uint4* lb = reinterpret_cast<const uint4*>(g_lineH + i * RES * 32);

        // ---- gather: 4 samples per iteration (one per 8-lane quarter) ----
#pragma unroll 2
        for (int j = 0; 4 * j < scount; j++) {
            int srcl = 4 * j + qid;            // sample slot for this quarter
            float X = __shfl_sync(0xFFFFFFFFu, mx, srcl);
            float Y = __shfl_sync(0xFFFFFFFFu, my, srcl);
            float Z = __shfl_sync(0xFFFFFFFFu, mz, srcl);
            // MAT_MODE = [[0,1],[0,2],[1,2]], VEC_MODE = [2,1,0]
            float c0 = (i == 2) ? Y : X;
            float c1 = (i == 0) ? Y : Z;
            float cv = (i == 0) ? Z : ((i == 1) ? Y : X);

            // plane bilinear (coords in [-1,1] -> ix,iy in [0,299])
            float ix = fmaf(c0, 149.5f, 149.5f);
            float iy = fmaf(c1, 149.5f, 149.5f);
            int xi = (int)ix, yi = (int)iy;    // trunc == floor (nonneg)
            float wx = ix - (float)xi, wy = iy - (float)yi;
            int x1 = min(xi + 1, RES - 1), y1 = min(yi + 1, RES - 1);
            int b0 = (yi * RES + xi) * 8 + lq; // texel = 8 uint4
            int b1 = (y1 * RES + xi) * 8 + lq;
            int dx = (x1 - xi) * 8;            // 0 or 8 uint4
            uint4 q00 = pb[b0], q01 = pb[b0 + dx];
            uint4 q10 = pb[b1], q11 = pb[b1 + dx];

            // line 1-D interp
            float iv = fmaf(cv, 149.5f, 149.5f);
            int vi = (int)iv;
            float wv = iv - (float)vi;
            int v1 = min(vi + 1, RES - 1);
            uint4 ql0 = lb[vi * 8 + lq], ql1 = lb[v1 * 8 + lq];

            float w0x = 1.f - wx, w0y = 1.f - wy;
            float w00 = w0x * w0y, w01 = wx * w0y, w10 = w0x * wy, w11 = wx * wy;
            float wv0 = 1.f - wv;

            const __half2* h00 = reinterpret_cast<const __half2*>(&q00);
            const __half2* h01 = reinterpret_cast<const __half2*>(&q01);
            const __half2* h10 = reinterpret_cast<const __half2*>(&q10);
            const __half2* h11 = reinterpret_cast<const __half2*>(&q11);
            const __half2* hl0 = reinterpret_cast<const __half2*>(&ql0);
            const __half2* hl1 = reinterpret_cast<const __half2*>(&ql1);

            float px[8];
#pragma unroll
            for (int k = 0; k < 4; k++) {
                float2 a00 = __half22float2(h00[k]);
                float2 a01 = __half22float2(h01[k]);
                float2 a10 = __half22float2(h10[k]);
                float2 a11 = __half22float2(h11[k]);
                float2 l0  = __half22float2(hl0[k]);
                float2 l1  = __half22float2(hl1[k]);
                float fx = fmaf(a00.x, w00, fmaf(a01.x, w01, fmaf(a10.x, w10, a11.x * w11)));
                float fy = fmaf(a00.y, w00, fmaf(a01.y, w01, fmaf(a10.y, w10, a11.y * w11)));
                float lfx = fmaf(l0.x, wv0, l1.x * wv);
                float lfy = fmaf(l0.y, wv0, l1.y * wv);
                px[2 * k]     = fx * lfx;
                px[2 * k + 1] = fy * lfy;
            }

            int row = w * 32 + srcl;
            if (lq < 6) {                      // app channels 8lq..8lq+7
                float* dst = smemV + row * ROWS + 8 * lq;
                *reinterpret_cast<float4*>(dst)     = make_float4(px[0], px[1], px[2], px[3]);
                *reinterpret_cast<float4*>(dst + 4) = make_float4(px[4], px[5], px[6], px[7]);
            }
            // density channels 48..63 in lanes lq=6,7
            float d = (lq >= 6) ? (px[0] + px[1] + px[2] + px[3]
                                 + px[4] + px[5] + px[6] + px[7]) : 0.f;
            d += __shfl_xor_sync(0xFFFFFFFFu, d, 1);
            if (lq == 6) {
                if (i == 0) smemD[row] = d; else smemD[row] += d;
            }
        }
        __syncwarp();

        // ---- GEMM chunk: lane = (sample pair pr, d-half h) ----
        {
            const float* row0 = smemV + (w * 32 + 2 * pr) * ROWS;
            const float* row1 = row0 + ROWS;
            const int wbase0 = 3 * h;          // h0: ull2 0..3 (d0..15); h1: 3..6 (d12..27)
#pragma unroll 2
            for (int k4 = 0; k4 < NC_A; k4 += 4) {
                float4 v0 = *reinterpret_cast<const float4*>(row0 + k4);
                float4 v1 = *reinterpret_cast<const float4*>(row1 + k4);
                float va[4] = {v0.x, v0.y, v0.z, v0.w};
                float vb[4] = {v1.x, v1.y, v1.z, v1.w};
#pragma unroll
                for (int j = 0; j < 4; j++) {
                    unsigned long long a0, a1;
                    asm("mov.b64 %0, {%1, %1};" : "=l"(a0) : "r"(__float_as_uint(va[j])));
                    asm("mov.b64 %0, {%1, %1};" : "=l"(a1) : "r"(__float_as_uint(vb[j])));
                    int k = i * NC_A + k4 + j;
                    const ulonglong2* wp = smemW + k * 7 + wbase0;
#pragma unroll
                    for (int q = 0; q < 4; q++) {
                        ulonglong2 w2 = wp[q];
                        asm("fma.rn.f32x2 %0, %1, %2, %0;" : "+l"(acc[2 * q])         : "l"(a0), "l"(w2.x));
                        asm("fma.rn.f32x2 %0, %1, %2, %0;" : "+l"(acc[2 * q + 1])     : "l"(a0), "l"(w2.y));
                        asm("fma.rn.f32x2 %0, %1, %2, %0;" : "+l"(acc[8 + 2 * q])     : "l"(a1), "l"(w2.x));
                        asm("fma.rn.f32x2 %0, %1, %2, %0;" : "+l"(acc[8 + 2 * q + 1]) : "l"(a1), "l"(w2.y));
                    }
                }
            }
        }
        __syncwarp();   // GEMM chunk done before next i overwrites rows (same warp)
    }

    // ---- epilogue: write acc to smem rows (skip the overlapped pairs), sigma, store ----
#pragma unroll
    for (int m = 0; m < 2; m++) {
        int sloc = 2 * pr + m;                 // sample slot in warp
        if (sbase + sloc < N) {
            float* rw = smemV + (w * 32 + sloc) * ROWS;
            // h0 owns pairs j=0..6 -> d = 2j, 2j+1 (d0..13)
            // h1 owns pairs j=1..7 -> d = 12+2j, 13+2j (d14..27; d27 pad, unread)
            int jlo = h ? 1 : 0, jhi = h ? 8 : 7;
            int dofs = h ? 12 : 0;
#pragma unroll
            for (int j = 0; j < 8; j++) {
                if (j >= jlo && j < jhi) {
                    unsigned int lo, hi;
                    asm("mov.b64 {%0, %1}, %2;" : "=r"(lo), "=r"(hi) : "l"(acc[8 * m + j]));
                    rw[dofs + 2 * j]     = __uint_as_float(lo);
                    rw[dofs + 2 * j + 1] = __uint_as_float(hi);
                }
            }
        }
    }
    if (blockStart + tid < N && lane < 32) {
        // sigma store: one per sample, use lane = sample slot mapping
        outSigma[blockStart + tid] = smemD[tid];
    }
    __syncwarp();
    if (scount > 0) {
        int cnt = scount * APP_DIM;
        size_t obase = (size_t)sbase * APP_DIM;
        for (int idx = lane; idx < cnt; idx += 32) {
            int s2 = idx / APP_DIM;
            int d2 = idx - s2 * APP_DIM;
            outApp[obase + idx] = smemV[(w * 32 + s2) * ROWS + d2];
        }
    }
}

extern "C" void kernel_launch(void* const* d_in, const int* in_sizes, int n_in,
                              void* d_out, int out_size) {
    const float* xyz   = (const float*)d_in[0];
    const float* plane = (const float*)d_in[1];
    const float* line  = (const float*)d_in[2];
    const float* W     = (const float*)d_in[3];
    int N = in_sizes[0] / 3;

    float* outSigma = (float*)d_out;
    float* outApp   = outSigma + N;

    pack_W_k<<<(KDIM * NPAIR + 255) / 256, 256>>>(W);
    transpose_planes_k<<<dim3((RES + 31) / 32, NCH / 32, 3 * RES), dim3(32, 8)>>>(plane);
    transpose_lines_k<<<(3 * RES * 32 + 255) / 256, 256>>>(line);

    int grid = (N + 127) / 128;
    tensorf_main<<<grid, 128>>>(xyz, outSigma, outApp, N);
}